// round 1
// baseline (speedup 1.0000x reference)
#include <cuda_runtime.h>
#include <math.h>

// ---------------------------------------------------------------------------
// StylePredictor forward: B=16, T=1024, D=256, H=2, DK=128, convK=5
// All fp32. Scratch lives in __device__ globals (no allocation).
// ---------------------------------------------------------------------------

constexpr int Bn  = 16;
constexpr int Tn  = 1024;
constexpr int Dn  = 256;
constexpr int Hn  = 2;
constexpr int Kc  = 5;
constexpr int Mn  = Bn * Tn;          // 16384 rows
constexpr float SCALE_ATTN = 1.0f / 16.0f;   // 1/sqrt(256)

__device__ float g_h1[Mn * Dn];
__device__ float g_h2[Mn * Dn];
__device__ float g_h3[Mn * Dn];
__device__ float g_res[Mn * Dn];
__device__ float g_q[Mn * Dn];
__device__ float g_k[Mn * Dn];
__device__ float g_v[Mn * Dn];
__device__ float g_attn[Mn * Dn];
__device__ float g_h5[Mn * Dn];
__device__ float g_convy[Mn * 2 * Dn];
__device__ float g_scores[(size_t)Bn * Hn * Tn * Tn];   // 134 MB
__device__ float g_wt[Kc * Dn * 2 * Dn];                // conv weight re-layout
__device__ float g_S[Bn * Dn];
__device__ float g_cinv[Bn];
__device__ unsigned char g_mask[Mn];

__device__ __forceinline__ float mishf(float x) {
    float sp = (x > 15.f) ? x : log1pf(__expf(x));
    return x * tanhf(sp);
}
__device__ __forceinline__ float sigmoidf(float x) {
    return 1.f / (1.f + __expf(-x));
}

// ---------------------------------------------------------------------------
// Mask normalization: detect u8 / i32 / f32 storage of the boolean mask and
// write canonical u8 into g_mask. Single block; deterministic in the input.
// ---------------------------------------------------------------------------
__global__ void mask_prepare(const unsigned char* __restrict__ raw) {
    __shared__ int s_nz1, s_f3;
    if (threadIdx.x == 0) { s_nz1 = 0; s_f3 = 0; }
    __syncthreads();
    int lnz = 0, lf = 0;
    for (int i = threadIdx.x; i < Mn; i += blockDim.x) {
        unsigned char v = raw[i];
        if ((i & 3) != 0 && v != 0) lnz++;
        if ((i & 3) == 3 && v == 0x3F) lf++;
    }
    atomicAdd(&s_nz1, lnz);
    atomicAdd(&s_f3, lf);
    __syncthreads();
    int mode = (s_f3 > 0) ? 2 : ((s_nz1 > 0) ? 0 : 1);  // 0=u8 1=i32 2=f32
    for (int i = threadIdx.x; i < Mn; i += blockDim.x) {
        unsigned char m;
        if (mode == 0)      m = (raw[i] != 0);
        else if (mode == 1) m = (((const int*)raw)[i] != 0);
        else                m = (((const float*)raw)[i] != 0.f);
        g_mask[i] = m;
    }
}

// ---------------------------------------------------------------------------
// GEMM TN: C = epi( A[M,K](lda) @ B[N,K](ldb)^T )
// 128x128 tile, BK=16, 256 threads, 8x8 per thread. No bounds checks: all
// dims used here are multiples of the tiles. Optional batch (z) decomposition.
// EPI: 0 = +bias, 1 = mish(+bias), 2 = +bias+res, 3 = *scale
// ---------------------------------------------------------------------------
template <int EPI>
__global__ void __launch_bounds__(256)
gemm_tn(const float* __restrict__ A, const float* __restrict__ Bm,
        const float* __restrict__ bias, const float* __restrict__ res,
        float* __restrict__ C,
        int K, int lda, int ldb, int ldc,
        int Hdec, long sAb, long sAh, long sBb, long sBh, long sCb, long sCh,
        float scale) {
    int z  = blockIdx.z;
    int zb = z / Hdec, zh = z - zb * Hdec;
    A  += zb * sAb + zh * sAh;
    Bm += zb * sBb + zh * sBh;
    C  += zb * sCb + zh * sCh;

    __shared__ float As[16][132];
    __shared__ float Bs[16][132];
    const int m0 = blockIdx.y * 128;
    const int n0 = blockIdx.x * 128;
    const int tid = threadIdx.x;
    const int tx = tid & 15, ty = tid >> 4;
    const int ar = tid >> 2;
    const int ac = (tid & 3) << 2;

    float acc[8][8];
#pragma unroll
    for (int i = 0; i < 8; i++)
#pragma unroll
        for (int j = 0; j < 8; j++) acc[i][j] = 0.f;

    for (int kt = 0; kt < K; kt += 16) {
#pragma unroll
        for (int p = 0; p < 2; p++) {
            int r = ar + p * 64;
            float4 va = *(const float4*)(A + (size_t)(m0 + r) * lda + kt + ac);
            As[ac + 0][r] = va.x; As[ac + 1][r] = va.y;
            As[ac + 2][r] = va.z; As[ac + 3][r] = va.w;
            float4 vb = *(const float4*)(Bm + (size_t)(n0 + r) * ldb + kt + ac);
            Bs[ac + 0][r] = vb.x; Bs[ac + 1][r] = vb.y;
            Bs[ac + 2][r] = vb.z; Bs[ac + 3][r] = vb.w;
        }
        __syncthreads();
#pragma unroll
        for (int k = 0; k < 16; k++) {
            float af[8], bfv[8];
#pragma unroll
            for (int i = 0; i < 8; i++) af[i] = As[k][ty * 8 + i];
#pragma unroll
            for (int j = 0; j < 8; j++) bfv[j] = Bs[k][tx * 8 + j];
#pragma unroll
            for (int i = 0; i < 8; i++)
#pragma unroll
                for (int j = 0; j < 8; j++)
                    acc[i][j] = fmaf(af[i], bfv[j], acc[i][j]);
        }
        __syncthreads();
    }

#pragma unroll
    for (int i = 0; i < 8; i++) {
        int m = m0 + ty * 8 + i;
#pragma unroll
        for (int j = 0; j < 8; j++) {
            int n = n0 + tx * 8 + j;
            float v = acc[i][j];
            if (EPI == 0)      v += bias[n];
            else if (EPI == 1) v = mishf(v + bias[n]);
            else if (EPI == 2) v = v + bias[n] + res[(size_t)m * ldc + n];
            else               v *= scale;
            C[(size_t)m * ldc + n] = v;
        }
    }
}

// ---------------------------------------------------------------------------
// GEMM NN: C = A[M,K](lda) @ B[K,N](ldb). Used for attention P@V (batched).
// ---------------------------------------------------------------------------
__global__ void __launch_bounds__(256)
gemm_nn(const float* __restrict__ A, const float* __restrict__ B2,
        float* __restrict__ C,
        int K, int lda, int ldb, int ldc,
        int Hdec, long sAb, long sAh, long sBb, long sBh, long sCb, long sCh) {
    int z  = blockIdx.z;
    int zb = z / Hdec, zh = z - zb * Hdec;
    A  += zb * sAb + zh * sAh;
    B2 += zb * sBb + zh * sBh;
    C  += zb * sCb + zh * sCh;

    __shared__ float As[16][132];
    __shared__ float Bs[16][132];
    const int m0 = blockIdx.y * 128;
    const int n0 = blockIdx.x * 128;
    const int tid = threadIdx.x;
    const int tx = tid & 15, ty = tid >> 4;
    const int ar = tid >> 2;
    const int ac = (tid & 3) << 2;
    const int br = tid >> 5;
    const int bc = (tid & 31) << 2;

    float acc[8][8];
#pragma unroll
    for (int i = 0; i < 8; i++)
#pragma unroll
        for (int j = 0; j < 8; j++) acc[i][j] = 0.f;

    for (int kt = 0; kt < K; kt += 16) {
#pragma unroll
        for (int p = 0; p < 2; p++) {
            int r = ar + p * 64;
            float4 va = *(const float4*)(A + (size_t)(m0 + r) * lda + kt + ac);
            As[ac + 0][r] = va.x; As[ac + 1][r] = va.y;
            As[ac + 2][r] = va.z; As[ac + 3][r] = va.w;
            int rk = br + p * 8;
            *(float4*)&Bs[rk][bc] =
                *(const float4*)(B2 + (size_t)(kt + rk) * ldb + n0 + bc);
        }
        __syncthreads();
#pragma unroll
        for (int k = 0; k < 16; k++) {
            float af[8], bfv[8];
#pragma unroll
            for (int i = 0; i < 8; i++) af[i] = As[k][ty * 8 + i];
#pragma unroll
            for (int j = 0; j < 8; j++) bfv[j] = Bs[k][tx * 8 + j];
#pragma unroll
            for (int i = 0; i < 8; i++)
#pragma unroll
                for (int j = 0; j < 8; j++)
                    acc[i][j] = fmaf(af[i], bfv[j], acc[i][j]);
        }
        __syncthreads();
    }

#pragma unroll
    for (int i = 0; i < 8; i++) {
        int m = m0 + ty * 8 + i;
#pragma unroll
        for (int j = 0; j < 8; j++) {
            int n = n0 + tx * 8 + j;
            C[(size_t)m * ldc + n] = acc[i][j];
        }
    }
}

// ---------------------------------------------------------------------------
// Conv weight re-layout: cW[oc, ic, kk] (torch [2D, D, K]) -> Wt[kk*D+ic][oc]
// ---------------------------------------------------------------------------
__global__ void wtrans(const float* __restrict__ cW, float* __restrict__ Wt) {
    int idx = blockIdx.x * blockDim.x + threadIdx.x;
    if (idx >= Kc * Dn * 2 * Dn) return;
    int oc = idx & 511;           // % 512
    int rest = idx >> 9;          // kk*256 + ic
    int ic = rest & 255;
    int kk = rest >> 8;
    Wt[idx] = cW[((size_t)oc * Dn + ic) * Kc + kk];
}

// ---------------------------------------------------------------------------
// Conv1d as implicit GEMM: Y[m, oc] = bias[oc] +
//   sum_{kk, ic} Hin[(b, t+kk-2), ic] * Wt[kk*256+ic][oc]   (zero pad in t)
// M=16384, N=512, K=1280.
// ---------------------------------------------------------------------------
__global__ void __launch_bounds__(256)
conv_gemm(const float* __restrict__ Hin, const float* __restrict__ Wt,
          const float* __restrict__ bias, float* __restrict__ Y) {
    __shared__ float As[16][132];
    __shared__ float Bs[16][132];
    const int m0 = blockIdx.y * 128;
    const int n0 = blockIdx.x * 128;
    const int tid = threadIdx.x;
    const int tx = tid & 15, ty = tid >> 4;
    const int ar = tid >> 2;
    const int ac = (tid & 3) << 2;
    const int br = tid >> 5;
    const int bc = (tid & 31) << 2;

    float acc[8][8];
#pragma unroll
    for (int i = 0; i < 8; i++)
#pragma unroll
        for (int j = 0; j < 8; j++) acc[i][j] = 0.f;

    for (int kt = 0; kt < Kc * Dn; kt += 16) {
        int kk = kt >> 8;
        int dt = kk - 2;
        int ic = (kt & 255) + ac;
#pragma unroll
        for (int p = 0; p < 2; p++) {
            int r = ar + p * 64;
            int m = m0 + r;
            int t = m & (Tn - 1);
            float4 va = make_float4(0.f, 0.f, 0.f, 0.f);
            if ((unsigned)(t + dt) < (unsigned)Tn)
                va = *(const float4*)(Hin + (size_t)(m + dt) * Dn + ic);
            As[ac + 0][r] = va.x; As[ac + 1][r] = va.y;
            As[ac + 2][r] = va.z; As[ac + 3][r] = va.w;
            int rk = br + p * 8;
            *(float4*)&Bs[rk][bc] =
                *(const float4*)(Wt + (size_t)(kt + rk) * (2 * Dn) + n0 + bc);
        }
        __syncthreads();
#pragma unroll
        for (int k = 0; k < 16; k++) {
            float af[8], bfv[8];
#pragma unroll
            for (int i = 0; i < 8; i++) af[i] = As[k][ty * 8 + i];
#pragma unroll
            for (int j = 0; j < 8; j++) bfv[j] = Bs[k][tx * 8 + j];
#pragma unroll
            for (int i = 0; i < 8; i++)
#pragma unroll
                for (int j = 0; j < 8; j++)
                    acc[i][j] = fmaf(af[i], bfv[j], acc[i][j]);
        }
        __syncthreads();
    }

#pragma unroll
    for (int i = 0; i < 8; i++) {
        int m = m0 + ty * 8 + i;
#pragma unroll
        for (int j = 0; j < 8; j++) {
            int n = n0 + tx * 8 + j;
            Y[(size_t)m * (2 * Dn) + n] = acc[i][j] + bias[n];
        }
    }
}

// GLU gate + residual (optionally apply mask-zeroing)
template <bool MASKED>
__global__ void glu_kernel(const float* __restrict__ Hin,
                           const float* __restrict__ Y,
                           float* __restrict__ Out) {
    int idx = blockIdx.x * blockDim.x + threadIdx.x;
    if (idx >= Mn * Dn) return;
    int m = idx >> 8;
    int n = idx & 255;
    float a = Y[(size_t)m * 512 + n];
    float g = Y[(size_t)m * 512 + 256 + n];
    float v = Hin[idx] + a * sigmoidf(g);
    if (MASKED && g_mask[m]) v = 0.f;
    Out[idx] = v;
}

// Row softmax over 1024 keys with key-mask (masked keys -> 0 prob). In place.
__global__ void softmax_kernel(float* __restrict__ Sc) {
    __shared__ float red[256];
    int row = blockIdx.x;              // z*T + q, z = b*H + h
    int b = row >> 11;                 // / (H*T)
    float* s = Sc + (size_t)row * Tn;
    const unsigned char* mk = g_mask + b * Tn;
    int tid = threadIdx.x;

    float mx = -1e30f;
    for (int k = tid; k < Tn; k += 256)
        if (!mk[k]) mx = fmaxf(mx, s[k]);
    red[tid] = mx;
    __syncthreads();
    for (int st = 128; st > 0; st >>= 1) {
        if (tid < st) red[tid] = fmaxf(red[tid], red[tid + st]);
        __syncthreads();
    }
    mx = red[0];
    __syncthreads();

    float sum = 0.f;
    for (int k = tid; k < Tn; k += 256) {
        float e = mk[k] ? 0.f : __expf(s[k] - mx);
        s[k] = e;
        sum += e;
    }
    red[tid] = sum;
    __syncthreads();
    for (int st = 128; st > 0; st >>= 1) {
        if (tid < st) red[tid] += red[tid + st];
        __syncthreads();
    }
    float inv = 1.f / red[0];
    for (int k = tid; k < Tn; k += 256) s[k] *= inv;
}

// Masked temporal sum: g_S[b,d] = sum_{t unmasked} h5[b,t,d]; g_cinv = 1/len
__global__ void pool_kernel(const float* __restrict__ H5) {
    int b = blockIdx.x;
    int d = threadIdx.x;
    float s = 0.f;
    int cnt = 0;
    for (int t = 0; t < Tn; t++) {
        if (!g_mask[b * Tn + t]) {
            s += H5[((size_t)b * Tn + t) * Dn + d];
            cnt++;
        }
    }
    g_S[b * Dn + d] = s;
    if (d == 0) g_cinv[b] = 1.f / (float)cnt;
}

// out[b,n] = (S_b @ Wf^T)[n]/len_b + bf[n]
__global__ void final_kernel(const float* __restrict__ Wf,
                             const float* __restrict__ bf,
                             float* __restrict__ out) {
    int b = blockIdx.x;
    int n = threadIdx.x;
    __shared__ float sb[Dn];
    sb[n] = g_S[b * Dn + n];
    __syncthreads();
    float acc = 0.f;
    const float* w = Wf + (size_t)n * Dn;
#pragma unroll 8
    for (int k = 0; k < Dn; k++) acc = fmaf(sb[k], w[k], acc);
    out[b * Dn + n] = acc * g_cinv[b] + bf[n];
}

// ---------------------------------------------------------------------------
extern "C" void kernel_launch(void* const* d_in, const int* in_sizes, int n_in,
                              void* d_out, int out_size) {
    (void)in_sizes; (void)n_in; (void)out_size;
    const float* x   = (const float*)d_in[0];
    const unsigned char* mraw = (const unsigned char*)d_in[1];
    const float* W1  = (const float*)d_in[2];
    const float* b1  = (const float*)d_in[3];
    const float* W2  = (const float*)d_in[4];
    const float* b2  = (const float*)d_in[5];
    const float* cW1 = (const float*)d_in[6];
    const float* cb1 = (const float*)d_in[7];
    const float* cW2 = (const float*)d_in[8];
    const float* cb2 = (const float*)d_in[9];
    const float* Wq  = (const float*)d_in[10];
    const float* bq  = (const float*)d_in[11];
    const float* Wk  = (const float*)d_in[12];
    const float* bk  = (const float*)d_in[13];
    const float* Wv  = (const float*)d_in[14];
    const float* bv  = (const float*)d_in[15];
    const float* Wo  = (const float*)d_in[16];
    const float* bo  = (const float*)d_in[17];
    const float* Wf  = (const float*)d_in[18];
    const float* bf  = (const float*)d_in[19];
    float* out = (float*)d_out;

    float *h1, *h2, *h3, *res, *q, *k, *v, *attn, *h5, *convy, *scores, *wt;
    cudaGetSymbolAddress((void**)&h1, g_h1);
    cudaGetSymbolAddress((void**)&h2, g_h2);
    cudaGetSymbolAddress((void**)&h3, g_h3);
    cudaGetSymbolAddress((void**)&res, g_res);
    cudaGetSymbolAddress((void**)&q, g_q);
    cudaGetSymbolAddress((void**)&k, g_k);
    cudaGetSymbolAddress((void**)&v, g_v);
    cudaGetSymbolAddress((void**)&attn, g_attn);
    cudaGetSymbolAddress((void**)&h5, g_h5);
    cudaGetSymbolAddress((void**)&convy, g_convy);
    cudaGetSymbolAddress((void**)&scores, g_scores);
    cudaGetSymbolAddress((void**)&wt, g_wt);

    // 0) normalize mask dtype
    mask_prepare<<<1, 1024>>>(mraw);

    dim3 gDense(2, 128, 1);       // N=256, M=16384
    dim3 gConv(4, 128, 1);        // N=512
    dim3 gScore(8, 8, 32);        // N=M=1024, 32 (b,h)
    dim3 gAV(1, 8, 32);           // N=128

    const long sQb = (long)Tn * Dn, sQh = 128;
    const long sSb = 2L * Tn * Tn, sSh = (long)Tn * Tn;

    // 1) spectral MLP
    gemm_tn<1><<<gDense, 256>>>(x,  W1, b1, nullptr, h1, Dn, Dn, Dn, Dn,
                                1, 0, 0, 0, 0, 0, 0, 1.f);
    gemm_tn<1><<<gDense, 256>>>(h1, W2, b2, nullptr, h2, Dn, Dn, Dn, Dn,
                                1, 0, 0, 0, 0, 0, 0, 1.f);

    // 2) Conv1dGLU x2
    wtrans<<<(Kc * Dn * 2 * Dn + 255) / 256, 256>>>(cW1, wt);
    conv_gemm<<<gConv, 256>>>(h2, wt, cb1, convy);
    glu_kernel<false><<<(Mn * Dn + 255) / 256, 256>>>(h2, convy, h3);

    wtrans<<<(Kc * Dn * 2 * Dn + 255) / 256, 256>>>(cW2, wt);
    conv_gemm<<<gConv, 256>>>(h3, wt, cb2, convy);
    glu_kernel<true><<<(Mn * Dn + 255) / 256, 256>>>(h3, convy, res);

    // 3) q,k,v projections
    gemm_tn<0><<<gDense, 256>>>(res, Wq, bq, nullptr, q, Dn, Dn, Dn, Dn,
                                1, 0, 0, 0, 0, 0, 0, 1.f);
    gemm_tn<0><<<gDense, 256>>>(res, Wk, bk, nullptr, k, Dn, Dn, Dn, Dn,
                                1, 0, 0, 0, 0, 0, 0, 1.f);
    gemm_tn<0><<<gDense, 256>>>(res, Wv, bv, nullptr, v, Dn, Dn, Dn, Dn,
                                1, 0, 0, 0, 0, 0, 0, 1.f);

    // 4) attention: scores = Q@K^T/temp (batched over b,h), softmax, P@V
    gemm_tn<3><<<gScore, 256>>>(q, k, nullptr, nullptr, scores,
                                128, Dn, Dn, Tn,
                                Hn, sQb, sQh, sQb, sQh, sSb, sSh, SCALE_ATTN);
    softmax_kernel<<<Bn * Hn * Tn, 256>>>(scores);
    gemm_nn<<<gAV, 256>>>(scores, v, attn,
                          Tn, Tn, Dn, Dn,
                          Hn, sSb, sSh, sQb, sQh, sQb, sQh);

    // 5) output projection + residual
    gemm_tn<2><<<gDense, 256>>>(attn, Wo, bo, res, h5, Dn, Dn, Dn, Dn,
                                1, 0, 0, 0, 0, 0, 0, 1.f);

    // 6) masked pool + tiny final GEMM (Wf folded after pooling)
    pool_kernel<<<Bn, Dn>>>(h5);
    final_kernel<<<Bn, Dn>>>(Wf, bf, out);
}

// round 3
// speedup vs baseline: 2.3681x; 2.3681x over previous
#include <cuda_runtime.h>
#include <math.h>

// ---------------------------------------------------------------------------
// StylePredictor forward: B=16, T=1024, D=256, H=2, DK=128, convK=5
// TF32 tensor-core GEMMs (mma.sync.m16n8k8), fp32 accumulate.
// ---------------------------------------------------------------------------

constexpr int Bn  = 16;
constexpr int Tn  = 1024;
constexpr int Dn  = 256;
constexpr int Hn  = 2;
constexpr int Kc  = 5;
constexpr int Mn  = Bn * Tn;                 // 16384 rows
constexpr float SCALE_ATTN = 1.0f / 16.0f;   // 1/sqrt(256)

__device__ float g_h1[Mn * Dn];
__device__ float g_h2[Mn * Dn];
__device__ float g_h3[Mn * Dn];
__device__ float g_res[Mn * Dn];
__device__ float g_q[Mn * Dn];
__device__ float g_k[Mn * Dn];
__device__ float g_v[Mn * Dn];
__device__ float g_attn[Mn * Dn];
__device__ float g_h5[Mn * Dn];
__device__ float g_convy[Mn * 2 * Dn];
__device__ float g_scores[(size_t)Bn * Hn * Tn * Tn];   // 134 MB
__device__ float g_wt[Kc * Dn * 2 * Dn];                // conv weight re-layout
__device__ float g_Sp[8][Bn * Dn];
__device__ float g_cinv[Bn];
__device__ unsigned char g_mask[Mn];

__device__ __forceinline__ float mishf(float x) {
    float sp = (x > 15.f) ? x : log1pf(__expf(x));
    return x * tanhf(sp);
}
__device__ __forceinline__ float sigmoidf(float x) {
    return 1.f / (1.f + __expf(-x));
}
__device__ __forceinline__ unsigned f2t(float x) {
    unsigned u;
    asm("cvt.rna.tf32.f32 %0, %1;" : "=r"(u) : "f"(x));
    return u;
}
__device__ __forceinline__ void mma_tf32(float* c, const unsigned* a,
                                         const unsigned* b) {
    asm volatile(
        "mma.sync.aligned.m16n8k8.row.col.f32.tf32.tf32.f32 "
        "{%0,%1,%2,%3}, {%4,%5,%6,%7}, {%8,%9}, {%0,%1,%2,%3};"
        : "+f"(c[0]), "+f"(c[1]), "+f"(c[2]), "+f"(c[3])
        : "r"(a[0]), "r"(a[1]), "r"(a[2]), "r"(a[3]), "r"(b[0]), "r"(b[1]));
}

// ---------------------------------------------------------------------------
// Mask normalization + per-batch 1/len. Single block, deterministic.
// ---------------------------------------------------------------------------
__global__ void mask_prepare(const unsigned char* __restrict__ raw) {
    __shared__ int s_nz1, s_f3;
    if (threadIdx.x == 0) { s_nz1 = 0; s_f3 = 0; }
    __syncthreads();
    int lnz = 0, lf = 0;
    for (int i = threadIdx.x; i < Mn; i += blockDim.x) {
        unsigned char v = raw[i];
        if ((i & 3) != 0 && v != 0) lnz++;
        if ((i & 3) == 3 && v == 0x3F) lf++;
    }
    atomicAdd(&s_nz1, lnz);
    atomicAdd(&s_f3, lf);
    __syncthreads();
    int mode = (s_f3 > 0) ? 2 : ((s_nz1 > 0) ? 0 : 1);  // 0=u8 1=i32 2=f32
    for (int i = threadIdx.x; i < Mn; i += blockDim.x) {
        unsigned char m;
        if (mode == 0)      m = (raw[i] != 0);
        else if (mode == 1) m = (((const int*)raw)[i] != 0);
        else                m = (((const float*)raw)[i] != 0.f);
        g_mask[i] = m;
    }
    __syncthreads();
    int w = threadIdx.x >> 5, l = threadIdx.x & 31;
    if (w < Bn) {
        int cnt = 0;
        for (int t = l; t < Tn; t += 32) cnt += (g_mask[w * Tn + t] == 0);
        for (int off = 16; off; off >>= 1)
            cnt += __shfl_down_sync(0xffffffffu, cnt, off);
        if (l == 0) g_cinv[w] = 1.f / (float)cnt;
    }
}

// ---------------------------------------------------------------------------
// Unified TF32 tensor-core GEMM.
//   BTRANS=true : C = A[M,K](lda) @ B[N,K](ldb)^T   (TN)
//   BTRANS=false: C = A[M,K](lda) @ B[K,N](ldb)     (NN)
//   CONV=true   : A rows gathered with time shift (implicit conv GEMM)
// 128x128 tile, BK=16, 256 threads (8 warps of 64x32), m16n8k8 tf32 MMA.
// EPI: 0 = +bias, 1 = mish(+bias), 2 = +bias+res, 3 = *scale
// ---------------------------------------------------------------------------
template <int EPI, bool BTRANS, bool CONV>
__global__ void __launch_bounds__(256)
mma_gemm(const float* __restrict__ A, const float* __restrict__ Bm,
         const float* __restrict__ bias, const float* __restrict__ res,
         float* __restrict__ C, int K, int lda, int ldb, int ldc,
         int Hdec, long sAb, long sAh, long sBb, long sBh, long sCb, long sCh,
         float scale) {
    if (!CONV) {
        int z = blockIdx.z;
        int zb = z / Hdec, zh = z - zb * Hdec;
        A  += zb * sAb + zh * sAh;
        Bm += zb * sBb + zh * sBh;
        C  += zb * sCb + zh * sCh;
    }
    // A tile: rows m (128) x k (16), row stride 36 words -> conflict-free frags
    // B TN tile: rows n x k, same layout. B NN tile: [16][136] k-major.
    __shared__ unsigned As[128 * 36];
    __shared__ unsigned Bs[128 * 36];

    const int m0 = blockIdx.y * 128;
    const int n0 = blockIdx.x * 128;
    const int tid  = threadIdx.x;
    const int warp = tid >> 5, lane = tid & 31;
    const int wr = warp >> 2, wc = warp & 3;     // 2 x 4 warp grid
    const int gid = lane >> 2, tig = lane & 3;   // mma fragment coords
    const int lr  = tid >> 2;                    // 0..63 (row loader)
    const int lc4 = (tid & 3) << 2;              // k col *4
    const int nr  = tid >> 5;                    // 0..7  (NN B loader)
    const int nc4 = (tid & 31) << 2;

    float acc[4][4][4];
#pragma unroll
    for (int i = 0; i < 4; i++)
#pragma unroll
        for (int j = 0; j < 4; j++)
#pragma unroll
            for (int q = 0; q < 4; q++) acc[i][j][q] = 0.f;

    for (int kt = 0; kt < K; kt += 16) {
        // ---- load A tile (tf32-converted) ----
#pragma unroll
        for (int p = 0; p < 2; p++) {
            int r = lr + p * 64;
            float4 v;
            if (CONV) {
                int dt = (kt >> 8) - 2;         // time shift for this k-block
                int m = m0 + r;
                int t = m & (Tn - 1);
                v = make_float4(0.f, 0.f, 0.f, 0.f);
                if ((unsigned)(t + dt) < (unsigned)Tn)
                    v = *(const float4*)(A + (size_t)(m + dt) * lda +
                                         (kt & 255) + lc4);
            } else {
                v = *(const float4*)(A + (size_t)(m0 + r) * lda + kt + lc4);
            }
            *(uint4*)&As[r * 36 + lc4] =
                make_uint4(f2t(v.x), f2t(v.y), f2t(v.z), f2t(v.w));
        }
        // ---- load B tile ----
#pragma unroll
        for (int p = 0; p < 2; p++) {
            if (BTRANS) {
                int r = lr + p * 64;
                float4 v = *(const float4*)(Bm + (size_t)(n0 + r) * ldb +
                                            kt + lc4);
                *(uint4*)&Bs[r * 36 + lc4] =
                    make_uint4(f2t(v.x), f2t(v.y), f2t(v.z), f2t(v.w));
            } else {
                int rk = nr + p * 8;
                float4 v = *(const float4*)(Bm + (size_t)(kt + rk) * ldb +
                                            n0 + nc4);
                *(uint4*)&Bs[rk * 136 + nc4] =
                    make_uint4(f2t(v.x), f2t(v.y), f2t(v.z), f2t(v.w));
            }
        }
        __syncthreads();

#pragma unroll
        for (int ks = 0; ks < 16; ks += 8) {
            unsigned af[4][4];
#pragma unroll
            for (int mt = 0; mt < 4; mt++) {
                int mr = wr * 64 + mt * 16 + gid;
                af[mt][0] = As[mr * 36 + ks + tig];
                af[mt][1] = As[(mr + 8) * 36 + ks + tig];
                af[mt][2] = As[mr * 36 + ks + tig + 4];
                af[mt][3] = As[(mr + 8) * 36 + ks + tig + 4];
            }
            unsigned bfr[4][2];
#pragma unroll
            for (int nt = 0; nt < 4; nt++) {
                int nc = wc * 32 + nt * 8 + gid;
                if (BTRANS) {
                    bfr[nt][0] = Bs[nc * 36 + ks + tig];
                    bfr[nt][1] = Bs[nc * 36 + ks + tig + 4];
                } else {
                    bfr[nt][0] = Bs[(ks + tig) * 136 + nc];
                    bfr[nt][1] = Bs[(ks + tig + 4) * 136 + nc];
                }
            }
#pragma unroll
            for (int mt = 0; mt < 4; mt++)
#pragma unroll
                for (int nt = 0; nt < 4; nt++)
                    mma_tf32(acc[mt][nt], af[mt], bfr[nt]);
        }
        __syncthreads();
    }

    // ---- epilogue ----
#pragma unroll
    for (int mt = 0; mt < 4; mt++) {
#pragma unroll
        for (int nt = 0; nt < 4; nt++) {
            int m = m0 + wr * 64 + mt * 16 + gid;
            int n = n0 + wc * 32 + nt * 8 + 2 * tig;
#pragma unroll
            for (int half = 0; half < 2; half++) {
                int mm = m + half * 8;
                float v0 = acc[mt][nt][half * 2 + 0];
                float v1 = acc[mt][nt][half * 2 + 1];
                if (EPI == 0) {
                    v0 += bias[n]; v1 += bias[n + 1];
                } else if (EPI == 1) {
                    v0 = mishf(v0 + bias[n]); v1 = mishf(v1 + bias[n + 1]);
                } else if (EPI == 2) {
                    v0 += bias[n]     + res[(size_t)mm * ldc + n];
                    v1 += bias[n + 1] + res[(size_t)mm * ldc + n + 1];
                } else {
                    v0 *= scale; v1 *= scale;
                }
                *(float2*)(C + (size_t)mm * ldc + n) = make_float2(v0, v1);
            }
        }
    }
}

// ---------------------------------------------------------------------------
// Conv weight re-layout: cW[oc, ic, kk] (torch [2D, D, K]) -> Wt[kk*D+ic][oc]
// ---------------------------------------------------------------------------
__global__ void wtrans(const float* __restrict__ cW, float* __restrict__ Wt) {
    int idx = blockIdx.x * blockDim.x + threadIdx.x;
    if (idx >= Kc * Dn * 2 * Dn) return;
    int oc = idx & 511;
    int rest = idx >> 9;
    int ic = rest & 255;
    int kk = rest >> 8;
    Wt[idx] = cW[((size_t)oc * Dn + ic) * Kc + kk];
}

// GLU gate + residual (optionally apply mask-zeroing)
template <bool MASKED>
__global__ void glu_kernel(const float* __restrict__ Hin,
                           const float* __restrict__ Y,
                           float* __restrict__ Out) {
    int idx = blockIdx.x * blockDim.x + threadIdx.x;
    if (idx >= Mn * Dn) return;
    int m = idx >> 8;
    int n = idx & 255;
    float a = Y[(size_t)m * 512 + n];
    float g = Y[(size_t)m * 512 + 256 + n];
    float v = Hin[idx] + a * sigmoidf(g);
    if (MASKED && g_mask[m]) v = 0.f;
    Out[idx] = v;
}

// Row softmax over 1024 keys with key-mask (masked keys -> 0 prob). In place.
__global__ void softmax_kernel(float* __restrict__ Sc) {
    __shared__ float red[256];
    int row = blockIdx.x;              // z*T + q, z = b*H + h
    int b = row >> 11;                 // / (H*T)
    float* s = Sc + (size_t)row * Tn;
    const unsigned char* mk = g_mask + b * Tn;
    int tid = threadIdx.x;

    float mx = -1e30f;
    for (int k = tid; k < Tn; k += 256)
        if (!mk[k]) mx = fmaxf(mx, s[k]);
    red[tid] = mx;
    __syncthreads();
    for (int st = 128; st > 0; st >>= 1) {
        if (tid < st) red[tid] = fmaxf(red[tid], red[tid + st]);
        __syncthreads();
    }
    mx = red[0];
    __syncthreads();

    float sum = 0.f;
    for (int k = tid; k < Tn; k += 256) {
        float e = mk[k] ? 0.f : __expf(s[k] - mx);
        s[k] = e;
        sum += e;
    }
    red[tid] = sum;
    __syncthreads();
    for (int st = 128; st > 0; st >>= 1) {
        if (tid < st) red[tid] += red[tid + st];
        __syncthreads();
    }
    float inv = 1.f / red[0];
    for (int k = tid; k < Tn; k += 256) s[k] *= inv;
}

// Masked temporal partial sums: g_Sp[chunk][b,d] over 128 t's each.
__global__ void pool_kernel(const float* __restrict__ H5) {
    int b = blockIdx.x;
    int chunk = blockIdx.y;
    int d = threadIdx.x;
    float s = 0.f;
    int t0 = chunk * 128;
    for (int t = t0; t < t0 + 128; t++)
        if (!g_mask[b * Tn + t])
            s += H5[((size_t)b * Tn + t) * Dn + d];
    g_Sp[chunk][b * Dn + d] = s;
}

// out[b,n] = (S_b @ Wf^T)[n]/len_b + bf[n]
__global__ void final_kernel(const float* __restrict__ Wf,
                             const float* __restrict__ bf,
                             float* __restrict__ out) {
    int b = blockIdx.x;
    int n = threadIdx.x;
    __shared__ float sb[Dn];
    float s = 0.f;
#pragma unroll
    for (int c = 0; c < 8; c++) s += g_Sp[c][b * Dn + n];
    sb[n] = s;
    __syncthreads();
    float acc = 0.f;
    const float* w = Wf + (size_t)n * Dn;
#pragma unroll 8
    for (int k = 0; k < Dn; k++) acc = fmaf(sb[k], w[k], acc);
    out[b * Dn + n] = acc * g_cinv[b] + bf[n];
}

// ---------------------------------------------------------------------------
extern "C" void kernel_launch(void* const* d_in, const int* in_sizes, int n_in,
                              void* d_out, int out_size) {
    (void)in_sizes; (void)n_in; (void)out_size;
    const float* x   = (const float*)d_in[0];
    const unsigned char* mraw = (const unsigned char*)d_in[1];
    const float* W1  = (const float*)d_in[2];
    const float* b1  = (const float*)d_in[3];
    const float* W2  = (const float*)d_in[4];
    const float* b2  = (const float*)d_in[5];
    const float* cW1 = (const float*)d_in[6];
    const float* cb1 = (const float*)d_in[7];
    const float* cW2 = (const float*)d_in[8];
    const float* cb2 = (const float*)d_in[9];
    const float* Wq  = (const float*)d_in[10];
    const float* bq  = (const float*)d_in[11];
    const float* Wk  = (const float*)d_in[12];
    const float* bk  = (const float*)d_in[13];
    const float* Wv  = (const float*)d_in[14];
    const float* bv  = (const float*)d_in[15];
    const float* Wo  = (const float*)d_in[16];
    const float* bo  = (const float*)d_in[17];
    const float* Wf  = (const float*)d_in[18];
    const float* bf  = (const float*)d_in[19];
    float* out = (float*)d_out;

    float *h1, *h2, *h3, *res, *q, *k, *v, *attn, *h5, *convy, *scores, *wt;
    cudaGetSymbolAddress((void**)&h1, g_h1);
    cudaGetSymbolAddress((void**)&h2, g_h2);
    cudaGetSymbolAddress((void**)&h3, g_h3);
    cudaGetSymbolAddress((void**)&res, g_res);
    cudaGetSymbolAddress((void**)&q, g_q);
    cudaGetSymbolAddress((void**)&k, g_k);
    cudaGetSymbolAddress((void**)&v, g_v);
    cudaGetSymbolAddress((void**)&attn, g_attn);
    cudaGetSymbolAddress((void**)&h5, g_h5);
    cudaGetSymbolAddress((void**)&convy, g_convy);
    cudaGetSymbolAddress((void**)&scores, g_scores);
    cudaGetSymbolAddress((void**)&wt, g_wt);

    // 0) normalize mask dtype + per-batch inverse lengths
    mask_prepare<<<1, 1024>>>(mraw);

    dim3 gDense(2, 128, 1);       // N=256, M=16384
    dim3 gConv(4, 128, 1);        // N=512
    dim3 gScore(8, 8, 32);        // N=M=1024, 32 (b,h)
    dim3 gAV(1, 8, 32);           // N=128

    const long sQb = (long)Tn * Dn, sQh = 128;
    const long sSb = 2L * Tn * Tn, sSh = (long)Tn * Tn;

    // 1) spectral MLP (Linear + Mish) x2
    mma_gemm<1, true, false><<<gDense, 256>>>(x,  W1, b1, nullptr, h1,
        Dn, Dn, Dn, Dn, 1, 0, 0, 0, 0, 0, 0, 1.f);
    mma_gemm<1, true, false><<<gDense, 256>>>(h1, W2, b2, nullptr, h2,
        Dn, Dn, Dn, Dn, 1, 0, 0, 0, 0, 0, 0, 1.f);

    // 2) Conv1dGLU x2 (implicit GEMM, K=1280)
    wtrans<<<(Kc * Dn * 2 * Dn + 255) / 256, 256>>>(cW1, wt);
    mma_gemm<0, false, true><<<gConv, 256>>>(h2, wt, cb1, nullptr, convy,
        Kc * Dn, Dn, 2 * Dn, 2 * Dn, 1, 0, 0, 0, 0, 0, 0, 1.f);
    glu_kernel<false><<<(Mn * Dn + 255) / 256, 256>>>(h2, convy, h3);

    wtrans<<<(Kc * Dn * 2 * Dn + 255) / 256, 256>>>(cW2, wt);
    mma_gemm<0, false, true><<<gConv, 256>>>(h3, wt, cb2, nullptr, convy,
        Kc * Dn, Dn, 2 * Dn, 2 * Dn, 1, 0, 0, 0, 0, 0, 0, 1.f);
    glu_kernel<true><<<(Mn * Dn + 255) / 256, 256>>>(h3, convy, res);

    // 3) q,k,v projections
    mma_gemm<0, true, false><<<gDense, 256>>>(res, Wq, bq, nullptr, q,
        Dn, Dn, Dn, Dn, 1, 0, 0, 0, 0, 0, 0, 1.f);
    mma_gemm<0, true, false><<<gDense, 256>>>(res, Wk, bk, nullptr, k,
        Dn, Dn, Dn, Dn, 1, 0, 0, 0, 0, 0, 0, 1.f);
    mma_gemm<0, true, false><<<gDense, 256>>>(res, Wv, bv, nullptr, v,
        Dn, Dn, Dn, Dn, 1, 0, 0, 0, 0, 0, 0, 1.f);

    // 4) attention: scores = Q@K^T/temp (batched over b,h), softmax, P@V
    mma_gemm<3, true, false><<<gScore, 256>>>(q, k, nullptr, nullptr, scores,
        128, Dn, Dn, Tn, Hn, sQb, sQh, sQb, sQh, sSb, sSh, SCALE_ATTN);
    softmax_kernel<<<Bn * Hn * Tn, 256>>>(scores);
    mma_gemm<3, false, false><<<gAV, 256>>>(scores, v, nullptr, nullptr, attn,
        Tn, Tn, Dn, Dn, Hn, sSb, sSh, sQb, sQh, sQb, sQh, 1.f);

    // 5) output projection + residual
    mma_gemm<2, true, false><<<gDense, 256>>>(attn, Wo, bo, res, h5,
        Dn, Dn, Dn, Dn, 1, 0, 0, 0, 0, 0, 0, 1.f);

    // 6) masked pool (partials) + tiny final GEMM (Wf folded after pooling)
    pool_kernel<<<dim3(Bn, 8), Dn>>>(h5);
    final_kernel<<<Bn, Dn>>>(Wf, bf, out);
}

// round 4
// speedup vs baseline: 2.6870x; 1.1347x over previous
#include <cuda_runtime.h>
#include <math.h>

// ---------------------------------------------------------------------------
// StylePredictor forward: B=16, T=1024, D=256, H=2, DK=128, convK=5
// TF32 tensor-core GEMMs (mma.sync.m16n8k8), cp.async double-buffered.
// All GEMM operands pre-rounded to tf32 (rna) at their producers.
// ---------------------------------------------------------------------------

constexpr int Bn  = 16;
constexpr int Tn  = 1024;
constexpr int Dn  = 256;
constexpr int Hn  = 2;
constexpr int Kc  = 5;
constexpr int Mn  = Bn * Tn;                 // 16384 rows
constexpr float SCALE_ATTN = 1.0f / 16.0f;   // 1/sqrt(256)

constexpr int SM_STRIDE = 36;                // A/B-TN smem row stride (words)
constexpr int SM_NSTR   = 136;               // B-NN smem row stride (words)
constexpr int SM_BUF    = 4608;              // 128*36 words per tile buffer
constexpr int SMEM_BYTES = 4 * SM_BUF * 4;   // 2 bufs x (A+B) = 73728 B

__device__ float g_xr[Mn * Dn];
__device__ float g_h1[Mn * Dn];
__device__ float g_h2[Mn * Dn];
__device__ float g_h3[Mn * Dn];
__device__ float g_res[Mn * Dn];
__device__ float g_qkv[Mn * 3 * Dn];
__device__ float g_attn[Mn * Dn];
__device__ float g_h5[Mn * Dn];
__device__ float g_convy[Mn * 2 * Dn];
__device__ float g_scores[(size_t)Bn * Hn * Tn * Tn];   // 134 MB
__device__ float g_wt1[Kc * Dn * 2 * Dn];
__device__ float g_wt2[Kc * Dn * 2 * Dn];
__device__ float g_w1r[Dn * Dn];
__device__ float g_w2r[Dn * Dn];
__device__ float g_wor[Dn * Dn];
__device__ float g_wqkv[3 * Dn * Dn];
__device__ float g_bqkv[3 * Dn];
__device__ float g_Sp[8][Bn * Dn];
__device__ float g_cinv[Bn];
__device__ unsigned char g_mask[Mn];

__device__ __forceinline__ float mishf(float x) {
    float sp = (x > 15.f) ? x : log1pf(__expf(x));
    return x * tanhf(sp);
}
__device__ __forceinline__ float sigmoidf(float x) {
    return 1.f / (1.f + __expf(-x));
}
__device__ __forceinline__ unsigned f2t(float x) {
    unsigned u;
    asm("cvt.rna.tf32.f32 %0, %1;" : "=r"(u) : "f"(x));
    return u;
}
__device__ __forceinline__ float rndf(float x) {
    return __uint_as_float(f2t(x));
}
__device__ __forceinline__ void mma_tf32(float* c, const unsigned* a,
                                         const unsigned* b) {
    asm volatile(
        "mma.sync.aligned.m16n8k8.row.col.f32.tf32.tf32.f32 "
        "{%0,%1,%2,%3}, {%4,%5,%6,%7}, {%8,%9}, {%0,%1,%2,%3};"
        : "+f"(c[0]), "+f"(c[1]), "+f"(c[2]), "+f"(c[3])
        : "r"(a[0]), "r"(a[1]), "r"(a[2]), "r"(a[3]), "r"(b[0]), "r"(b[1]));
}
__device__ __forceinline__ void cpa16(float* dst, const float* g) {
    unsigned s = (unsigned)__cvta_generic_to_shared(dst);
    asm volatile("cp.async.ca.shared.global [%0], [%1], 16;"
                 :: "r"(s), "l"(g) : "memory");
}
__device__ __forceinline__ void cpa16p(float* dst, const float* g, bool ok) {
    unsigned s = (unsigned)__cvta_generic_to_shared(dst);
    int sz = ok ? 16 : 0;
    asm volatile("cp.async.ca.shared.global [%0], [%1], 16, %2;"
                 :: "r"(s), "l"(g), "r"(sz) : "memory");
}

// ---------------------------------------------------------------------------
// Mask normalization + per-batch 1/len. Single block, deterministic.
// ---------------------------------------------------------------------------
__global__ void mask_prepare(const unsigned char* __restrict__ raw) {
    __shared__ int s_nz1, s_f3;
    if (threadIdx.x == 0) { s_nz1 = 0; s_f3 = 0; }
    __syncthreads();
    int lnz = 0, lf = 0;
    for (int i = threadIdx.x; i < Mn; i += blockDim.x) {
        unsigned char v = raw[i];
        if ((i & 3) != 0 && v != 0) lnz++;
        if ((i & 3) == 3 && v == 0x3F) lf++;
    }
    atomicAdd(&s_nz1, lnz);
    atomicAdd(&s_f3, lf);
    __syncthreads();
    int mode = (s_f3 > 0) ? 2 : ((s_nz1 > 0) ? 0 : 1);  // 0=u8 1=i32 2=f32
    for (int i = threadIdx.x; i < Mn; i += blockDim.x) {
        unsigned char m;
        if (mode == 0)      m = (raw[i] != 0);
        else if (mode == 1) m = (((const int*)raw)[i] != 0);
        else                m = (((const float*)raw)[i] != 0.f);
        g_mask[i] = m;
    }
    __syncthreads();
    int w = threadIdx.x >> 5, l = threadIdx.x & 31;
    if (w < Bn) {
        int cnt = 0;
        for (int t = l; t < Tn; t += 32) cnt += (g_mask[w * Tn + t] == 0);
        for (int off = 16; off; off >>= 1)
            cnt += __shfl_down_sync(0xffffffffu, cnt, off);
        if (l == 0) g_cinv[w] = 1.f / (float)cnt;
    }
}

// tf32-round a tensor
__global__ void roundt(const float* __restrict__ in, float* __restrict__ out,
                       int n) {
    int i = blockIdx.x * blockDim.x + threadIdx.x;
    if (i < n) out[i] = rndf(in[i]);
}

// Pack+round Wq/Wk/Wv -> [768,256]; biases (fp32, unrounded) -> [768]
__global__ void wpack(const float* __restrict__ Wq, const float* __restrict__ Wk,
                      const float* __restrict__ Wv, const float* __restrict__ bq,
                      const float* __restrict__ bk, const float* __restrict__ bv,
                      float* __restrict__ W, float* __restrict__ b) {
    int idx = blockIdx.x * blockDim.x + threadIdx.x;
    if (idx < 3 * Dn * Dn) {
        int which = idx >> 16;
        const float* src = which == 0 ? Wq : (which == 1 ? Wk : Wv);
        W[idx] = rndf(src[idx & 65535]);
    }
    if (idx < 3 * Dn) {
        const float* sb = idx < 256 ? bq : (idx < 512 ? bk : bv);
        b[idx] = sb[idx & 255];
    }
}

// Conv weight re-layout + round: cW[oc, ic, kk] -> Wt[kk*D+ic][oc]
__global__ void wtrans(const float* __restrict__ cW, float* __restrict__ Wt) {
    int idx = blockIdx.x * blockDim.x + threadIdx.x;
    if (idx >= Kc * Dn * 2 * Dn) return;
    int oc = idx & 511;
    int rest = idx >> 9;
    int ic = rest & 255;
    int kk = rest >> 8;
    Wt[idx] = rndf(cW[((size_t)oc * Dn + ic) * Kc + kk]);
}

// ---------------------------------------------------------------------------
// Unified TF32 tensor-core GEMM, cp.async 2-stage pipeline.
//   BTRANS=true : C = A[M,K](lda) @ B[N,K](ldb)^T   (TN)
//   BTRANS=false: C = A[M,K](lda) @ B[K,N](ldb)     (NN)
//   CONV=true   : A rows gathered with time shift (implicit conv GEMM)
// EPI: 0 = +bias, 1 = mish(+bias), 2 = +bias+res, 3 = *scale
// RND: tf32-round the stored output (for tensors feeding later GEMMs)
// ---------------------------------------------------------------------------
template <int EPI, bool BTRANS, bool CONV, bool RND>
__global__ void __launch_bounds__(256)
mma_gemm(const float* __restrict__ A, const float* __restrict__ Bm,
         const float* __restrict__ bias, const float* __restrict__ res,
         float* __restrict__ C, int K, int lda, int ldb, int ldc,
         int Hdec, long sAb, long sAh, long sBb, long sBh, long sCb, long sCh,
         float scale) {
    if (!CONV) {
        int z = blockIdx.z;
        int zb = z / Hdec, zh = z - zb * Hdec;
        A  += zb * sAb + zh * sAh;
        Bm += zb * sBb + zh * sBh;
        C  += zb * sCb + zh * sCh;
    }
    extern __shared__ float smemf[];
    float* Asb = smemf;                  // [2][4608]
    float* Bsb = smemf + 2 * SM_BUF;     // [2][4608]

    const int m0 = blockIdx.y * 128;
    const int n0 = blockIdx.x * 128;
    const int tid  = threadIdx.x;
    const int warp = tid >> 5, lane = tid & 31;
    const int wr = warp >> 2, wc = warp & 3;     // 2 x 4 warp grid
    const int gid = lane >> 2, tig = lane & 3;   // mma fragment coords
    const int lr  = tid >> 2;                    // 0..63 (row loader)
    const int lc4 = (tid & 3) << 2;              // k col *4
    const int nr  = tid >> 5;                    // 0..7  (NN B loader)
    const int nc4 = (tid & 31) << 2;

    auto load_tiles = [&](int buf, int kt) {
        float* As = Asb + buf * SM_BUF;
        float* Bs = Bsb + buf * SM_BUF;
#pragma unroll
        for (int p = 0; p < 2; p++) {
            int r = lr + p * 64;
            if (CONV) {
                int dt = (kt >> 8) - 2;
                int m = m0 + r;
                int t = m & (Tn - 1);
                bool ok = (unsigned)(t + dt) < (unsigned)Tn;
                const float* g = A + (size_t)(m + (ok ? dt : 0)) * lda +
                                 (kt & 255) + lc4;
                cpa16p(As + r * SM_STRIDE + lc4, g, ok);
            } else {
                cpa16(As + r * SM_STRIDE + lc4,
                      A + (size_t)(m0 + r) * lda + kt + lc4);
            }
            if (BTRANS) {
                cpa16(Bs + r * SM_STRIDE + lc4,
                      Bm + (size_t)(n0 + r) * ldb + kt + lc4);
            } else {
                int rk = nr + p * 8;
                cpa16(Bs + rk * SM_NSTR + nc4,
                      Bm + (size_t)(kt + rk) * ldb + n0 + nc4);
            }
        }
    };

    float acc[4][4][4];
#pragma unroll
    for (int i = 0; i < 4; i++)
#pragma unroll
        for (int j = 0; j < 4; j++)
#pragma unroll
            for (int q = 0; q < 4; q++) acc[i][j][q] = 0.f;

    load_tiles(0, 0);
    asm volatile("cp.async.commit_group;" ::: "memory");

    const int nIter = K >> 4;
    for (int it = 0; it < nIter; it++) {
        int buf = it & 1;
        if (it + 1 < nIter) {
            load_tiles(buf ^ 1, (it + 1) << 4);
            asm volatile("cp.async.commit_group;" ::: "memory");
            asm volatile("cp.async.wait_group 1;" ::: "memory");
        } else {
            asm volatile("cp.async.wait_group 0;" ::: "memory");
        }
        __syncthreads();

        const unsigned* As = (const unsigned*)(Asb + buf * SM_BUF);
        const unsigned* Bs = (const unsigned*)(Bsb + buf * SM_BUF);
#pragma unroll
        for (int ks = 0; ks < 16; ks += 8) {
            unsigned af[4][4];
#pragma unroll
            for (int mt = 0; mt < 4; mt++) {
                int mr = wr * 64 + mt * 16 + gid;
                af[mt][0] = As[mr * SM_STRIDE + ks + tig];
                af[mt][1] = As[(mr + 8) * SM_STRIDE + ks + tig];
                af[mt][2] = As[mr * SM_STRIDE + ks + tig + 4];
                af[mt][3] = As[(mr + 8) * SM_STRIDE + ks + tig + 4];
            }
            unsigned bfr[4][2];
#pragma unroll
            for (int nt = 0; nt < 4; nt++) {
                int nc = wc * 32 + nt * 8 + gid;
                if (BTRANS) {
                    bfr[nt][0] = Bs[nc * SM_STRIDE + ks + tig];
                    bfr[nt][1] = Bs[nc * SM_STRIDE + ks + tig + 4];
                } else {
                    bfr[nt][0] = Bs[(ks + tig) * SM_NSTR + nc];
                    bfr[nt][1] = Bs[(ks + tig + 4) * SM_NSTR + nc];
                }
            }
#pragma unroll
            for (int mt = 0; mt < 4; mt++)
#pragma unroll
                for (int nt = 0; nt < 4; nt++)
                    mma_tf32(acc[mt][nt], af[mt], bfr[nt]);
        }
        __syncthreads();
    }

    // ---- epilogue ----
#pragma unroll
    for (int mt = 0; mt < 4; mt++) {
#pragma unroll
        for (int nt = 0; nt < 4; nt++) {
            int m = m0 + wr * 64 + mt * 16 + gid;
            int n = n0 + wc * 32 + nt * 8 + 2 * tig;
#pragma unroll
            for (int half = 0; half < 2; half++) {
                int mm = m + half * 8;
                float v0 = acc[mt][nt][half * 2 + 0];
                float v1 = acc[mt][nt][half * 2 + 1];
                if (EPI == 0) {
                    v0 += bias[n]; v1 += bias[n + 1];
                } else if (EPI == 1) {
                    v0 = mishf(v0 + bias[n]); v1 = mishf(v1 + bias[n + 1]);
                } else if (EPI == 2) {
                    v0 += bias[n]     + res[(size_t)mm * ldc + n];
                    v1 += bias[n + 1] + res[(size_t)mm * ldc + n + 1];
                } else {
                    v0 *= scale; v1 *= scale;
                }
                if (RND) { v0 = rndf(v0); v1 = rndf(v1); }
                *(float2*)(C + (size_t)mm * ldc + n) = make_float2(v0, v1);
            }
        }
    }
}

// GLU gate + residual (optionally mask-zero); output tf32-rounded
template <bool MASKED>
__global__ void glu_kernel(const float* __restrict__ Hin,
                           const float* __restrict__ Y,
                           float* __restrict__ Out) {
    int idx = blockIdx.x * blockDim.x + threadIdx.x;
    if (idx >= Mn * Dn) return;
    int m = idx >> 8;
    int n = idx & 255;
    float a = Y[(size_t)m * 512 + n];
    float g = Y[(size_t)m * 512 + 256 + n];
    float v = Hin[idx] + a * sigmoidf(g);
    if (MASKED && g_mask[m]) v = 0.f;
    Out[idx] = rndf(v);
}

// Row softmax over 1024 keys with key-mask. Vectorized: one float4/thread.
// Stores tf32-rounded probabilities (they feed the PV GEMM).
__global__ void softmax_kernel(float* __restrict__ Sc) {
    __shared__ float sred[8];
    int row = blockIdx.x;              // z*T + q, z = b*H + h
    int b = row >> 11;
    float4* s4 = (float4*)(Sc + (size_t)row * Tn);
    const uchar4* mk4 = (const uchar4*)(g_mask + b * Tn);
    int tid = threadIdx.x, lane = tid & 31, wrp = tid >> 5;

    uchar4 m = mk4[tid];
    float4 v = s4[tid];
    float f0 = m.x ? -1e30f : v.x;
    float f1 = m.y ? -1e30f : v.y;
    float f2 = m.z ? -1e30f : v.z;
    float f3 = m.w ? -1e30f : v.w;
    float mx = fmaxf(fmaxf(f0, f1), fmaxf(f2, f3));
#pragma unroll
    for (int o = 16; o; o >>= 1)
        mx = fmaxf(mx, __shfl_xor_sync(0xffffffffu, mx, o));
    if (lane == 0) sred[wrp] = mx;
    __syncthreads();
    if (wrp == 0) {
        float t = sred[lane & 7];
#pragma unroll
        for (int o = 4; o; o >>= 1)
            t = fmaxf(t, __shfl_xor_sync(0xffffffffu, t, o));
        if (lane == 0) sred[0] = t;
    }
    __syncthreads();
    mx = sred[0];

    float e0 = m.x ? 0.f : __expf(v.x - mx);
    float e1 = m.y ? 0.f : __expf(v.y - mx);
    float e2 = m.z ? 0.f : __expf(v.z - mx);
    float e3 = m.w ? 0.f : __expf(v.w - mx);
    float sum = (e0 + e1) + (e2 + e3);
#pragma unroll
    for (int o = 16; o; o >>= 1)
        sum += __shfl_xor_sync(0xffffffffu, sum, o);
    __syncthreads();
    if (lane == 0) sred[wrp] = sum;
    __syncthreads();
    if (wrp == 0) {
        float t = sred[lane & 7];
#pragma unroll
        for (int o = 4; o; o >>= 1)
            t += __shfl_xor_sync(0xffffffffu, t, o);
        if (lane == 0) sred[0] = t;
    }
    __syncthreads();
    float inv = 1.f / sred[0];
    s4[tid] = make_float4(rndf(e0 * inv), rndf(e1 * inv),
                          rndf(e2 * inv), rndf(e3 * inv));
}

// Masked temporal partial sums: g_Sp[chunk][b,d] over 128 t's each.
__global__ void pool_kernel(const float* __restrict__ H5) {
    int b = blockIdx.x;
    int chunk = blockIdx.y;
    int d = threadIdx.x;
    float s = 0.f;
    int t0 = chunk * 128;
    for (int t = t0; t < t0 + 128; t++)
        if (!g_mask[b * Tn + t])
            s += H5[((size_t)b * Tn + t) * Dn + d];
    g_Sp[chunk][b * Dn + d] = s;
}

// out[b,n] = (S_b @ Wf^T)[n]/len_b + bf[n]
__global__ void final_kernel(const float* __restrict__ Wf,
                             const float* __restrict__ bf,
                             float* __restrict__ out) {
    int b = blockIdx.x;
    int n = threadIdx.x;
    __shared__ float sb[Dn];
    float s = 0.f;
#pragma unroll
    for (int c = 0; c < 8; c++) s += g_Sp[c][b * Dn + n];
    sb[n] = s;
    __syncthreads();
    float acc = 0.f;
    const float* w = Wf + (size_t)n * Dn;
#pragma unroll 8
    for (int k = 0; k < Dn; k++) acc = fmaf(sb[k], w[k], acc);
    out[b * Dn + n] = acc * g_cinv[b] + bf[n];
}

// ---------------------------------------------------------------------------
extern "C" void kernel_launch(void* const* d_in, const int* in_sizes, int n_in,
                              void* d_out, int out_size) {
    (void)in_sizes; (void)n_in; (void)out_size;
    const float* x   = (const float*)d_in[0];
    const unsigned char* mraw = (const unsigned char*)d_in[1];
    const float* W1  = (const float*)d_in[2];
    const float* b1  = (const float*)d_in[3];
    const float* W2  = (const float*)d_in[4];
    const float* b2  = (const float*)d_in[5];
    const float* cW1 = (const float*)d_in[6];
    const float* cb1 = (const float*)d_in[7];
    const float* cW2 = (const float*)d_in[8];
    const float* cb2 = (const float*)d_in[9];
    const float* Wq  = (const float*)d_in[10];
    const float* bq  = (const float*)d_in[11];
    const float* Wk  = (const float*)d_in[12];
    const float* bk  = (const float*)d_in[13];
    const float* Wv  = (const float*)d_in[14];
    const float* bv  = (const float*)d_in[15];
    const float* Wo  = (const float*)d_in[16];
    const float* bo  = (const float*)d_in[17];
    const float* Wf  = (const float*)d_in[18];
    const float* bf  = (const float*)d_in[19];
    float* out = (float*)d_out;

    float *xr, *h1, *h2, *h3, *res, *qkv, *attn, *h5, *convy, *scores;
    float *wt1, *wt2, *w1r, *w2r, *wor, *wqkvp, *bqkvp;
    cudaGetSymbolAddress((void**)&xr, g_xr);
    cudaGetSymbolAddress((void**)&h1, g_h1);
    cudaGetSymbolAddress((void**)&h2, g_h2);
    cudaGetSymbolAddress((void**)&h3, g_h3);
    cudaGetSymbolAddress((void**)&res, g_res);
    cudaGetSymbolAddress((void**)&qkv, g_qkv);
    cudaGetSymbolAddress((void**)&attn, g_attn);
    cudaGetSymbolAddress((void**)&h5, g_h5);
    cudaGetSymbolAddress((void**)&convy, g_convy);
    cudaGetSymbolAddress((void**)&scores, g_scores);
    cudaGetSymbolAddress((void**)&wt1, g_wt1);
    cudaGetSymbolAddress((void**)&wt2, g_wt2);
    cudaGetSymbolAddress((void**)&w1r, g_w1r);
    cudaGetSymbolAddress((void**)&w2r, g_w2r);
    cudaGetSymbolAddress((void**)&wor, g_wor);
    cudaGetSymbolAddress((void**)&wqkvp, g_wqkv);
    cudaGetSymbolAddress((void**)&bqkvp, g_bqkv);

    // raise dynamic smem limit for all GEMM instantiations
    cudaFuncSetAttribute(mma_gemm<1, true,  false, true >, cudaFuncAttributeMaxDynamicSharedMemorySize, SMEM_BYTES);
    cudaFuncSetAttribute(mma_gemm<0, false, true,  false>, cudaFuncAttributeMaxDynamicSharedMemorySize, SMEM_BYTES);
    cudaFuncSetAttribute(mma_gemm<0, true,  false, true >, cudaFuncAttributeMaxDynamicSharedMemorySize, SMEM_BYTES);
    cudaFuncSetAttribute(mma_gemm<3, true,  false, false>, cudaFuncAttributeMaxDynamicSharedMemorySize, SMEM_BYTES);
    cudaFuncSetAttribute(mma_gemm<3, false, false, true >, cudaFuncAttributeMaxDynamicSharedMemorySize, SMEM_BYTES);
    cudaFuncSetAttribute(mma_gemm<2, true,  false, false>, cudaFuncAttributeMaxDynamicSharedMemorySize, SMEM_BYTES);

    // 0) mask + operand pre-rounding / packing
    mask_prepare<<<1, 1024>>>(mraw);
    roundt<<<Mn * Dn / 256, 256>>>(x, xr, Mn * Dn);
    roundt<<<Dn * Dn / 256, 256>>>(W1, w1r, Dn * Dn);
    roundt<<<Dn * Dn / 256, 256>>>(W2, w2r, Dn * Dn);
    roundt<<<Dn * Dn / 256, 256>>>(Wo, wor, Dn * Dn);
    wpack<<<3 * Dn * Dn / 256, 256>>>(Wq, Wk, Wv, bq, bk, bv, wqkvp, bqkvp);
    wtrans<<<(Kc * Dn * 2 * Dn + 255) / 256, 256>>>(cW1, wt1);
    wtrans<<<(Kc * Dn * 2 * Dn + 255) / 256, 256>>>(cW2, wt2);

    dim3 gDense(2, 128, 1);       // N=256, M=16384
    dim3 gQKV(6, 128, 1);         // N=768
    dim3 gConv(4, 128, 1);        // N=512
    dim3 gScore(8, 8, 32);        // N=M=1024, 32 (b,h)
    dim3 gAV(1, 8, 32);           // N=128

    const long sQb = (long)Tn * 3 * Dn, sQh = 128;  // qkv views, ld=768
    const long sSb = 2L * Tn * Tn, sSh = (long)Tn * Tn;
    const long sCb = (long)Tn * Dn, sCh = 128;

    // 1) spectral MLP (Linear + Mish) x2
    mma_gemm<1, true, false, true><<<gDense, 256, SMEM_BYTES>>>(xr, w1r, b1,
        nullptr, h1, Dn, Dn, Dn, Dn, 1, 0, 0, 0, 0, 0, 0, 1.f);
    mma_gemm<1, true, false, true><<<gDense, 256, SMEM_BYTES>>>(h1, w2r, b2,
        nullptr, h2, Dn, Dn, Dn, Dn, 1, 0, 0, 0, 0, 0, 0, 1.f);

    // 2) Conv1dGLU x2 (implicit GEMM, K=1280)
    mma_gemm<0, false, true, false><<<gConv, 256, SMEM_BYTES>>>(h2, wt1, cb1,
        nullptr, convy, Kc * Dn, Dn, 2 * Dn, 2 * Dn, 1, 0, 0, 0, 0, 0, 0, 1.f);
    glu_kernel<false><<<(Mn * Dn + 255) / 256, 256>>>(h2, convy, h3);
    mma_gemm<0, false, true, false><<<gConv, 256, SMEM_BYTES>>>(h3, wt2, cb2,
        nullptr, convy, Kc * Dn, Dn, 2 * Dn, 2 * Dn, 1, 0, 0, 0, 0, 0, 0, 1.f);
    glu_kernel<true><<<(Mn * Dn + 255) / 256, 256>>>(h3, convy, res);

    // 3) fused q,k,v projection (N=768)
    mma_gemm<0, true, false, true><<<gQKV, 256, SMEM_BYTES>>>(res, wqkvp,
        bqkvp, nullptr, qkv, Dn, Dn, Dn, 3 * Dn, 1, 0, 0, 0, 0, 0, 0, 1.f);

    // 4) attention: scores = Q@K^T/temp, softmax, P@V
    mma_gemm<3, true, false, false><<<gScore, 256, SMEM_BYTES>>>(qkv,
        qkv + Dn, nullptr, nullptr, scores, 128, 3 * Dn, 3 * Dn, Tn,
        Hn, sQb, sQh, sQb, sQh, sSb, sSh, SCALE_ATTN);
    softmax_kernel<<<Bn * Hn * Tn, 256>>>(scores);
    mma_gemm<3, false, false, true><<<gAV, 256, SMEM_BYTES>>>(scores,
        qkv + 2 * Dn, nullptr, nullptr, attn, Tn, Tn, 3 * Dn, Dn,
        Hn, sSb, sSh, sQb, sQh, sCb, sCh, 1.f);

    // 5) output projection + residual
    mma_gemm<2, true, false, false><<<gDense, 256, SMEM_BYTES>>>(attn, wor,
        bo, res, h5, Dn, Dn, Dn, Dn, 1, 0, 0, 0, 0, 0, 0, 1.f);

    // 6) masked pool (partials) + tiny final GEMM (Wf folded after pooling)
    pool_kernel<<<dim3(Bn, 8), Dn>>>(h5);
    final_kernel<<<Bn, Dn>>>(Wf, bf, out);
}

// round 6
// speedup vs baseline: 4.2777x; 1.5920x over previous
#include <cuda_runtime.h>
#include <cuda_fp16.h>
#include <math.h>

// ---------------------------------------------------------------------------
// StylePredictor forward: B=16, T=1024, D=256, H=2, DK=128, convK=5
// FP16 tensor-core GEMMs (mma.sync.m16n8k16, fp32 accumulate), cp.async
// double-buffered. All intermediates fp16 (10-bit mantissa, same as tf32).
// Conv GLU fused into GEMM epilogue; V written transposed (PV becomes TN).
// ---------------------------------------------------------------------------

constexpr int Bn  = 16;
constexpr int Tn  = 1024;
constexpr int Dn  = 256;
constexpr int Hn  = 2;
constexpr int Kc  = 5;
constexpr int Mn  = Bn * Tn;                 // 16384 rows
constexpr float SCALE_ATTN = 1.0f / 16.0f;   // 1/sqrt(256)

// smem tile: 128 rows x 32 halves (64B) padded to 80B stride -> 10240 B/tile
constexpr int ROW_B   = 80;                  // bytes per smem row
constexpr int ROW_W   = 20;                  // words per smem row
constexpr int TILE_B  = 128 * ROW_B;         // 10240

__device__ __half g_xh[Mn * Dn];
__device__ __half g_h1[Mn * Dn];
__device__ __half g_h2[Mn * Dn];
__device__ __half g_h3[Mn * Dn];
__device__ __half g_res[Mn * Dn];
__device__ __half g_qk[Mn * 2 * Dn];
__device__ __half g_vt[Mn * Dn];             // [bh][128 d][1024 t]
__device__ __half g_attn[Mn * Dn];
__device__ float  g_h5[Mn * Dn];
__device__ __half g_scores[(size_t)Bn * Hn * Tn * Tn];   // 67 MB
__device__ __half g_wt1[2 * Dn * Kc * Dn];   // [512 j][1280 k] interleaved a/g
__device__ __half g_wt2[2 * Dn * Kc * Dn];
__device__ __half g_w1h[Dn * Dn];
__device__ __half g_w2h[Dn * Dn];
__device__ __half g_woh[Dn * Dn];
__device__ __half g_wvh[Dn * Dn];
__device__ __half g_wqk[2 * Dn * Dn];
__device__ float  g_bqk[2 * Dn];
__device__ float  g_Sp[8][Bn * Dn];
__device__ float  g_cinv[Bn];
__device__ unsigned char g_mask[Mn];

__device__ __forceinline__ float mishf(float x) {
    float sp = (x > 15.f) ? x : log1pf(__expf(x));
    return x * tanhf(sp);
}
__device__ __forceinline__ float sigmoidf(float x) {
    return 1.f / (1.f + __expf(-x));
}
__device__ __forceinline__ void mma_f16(float* c, const unsigned* a,
                                        const unsigned* b) {
    asm volatile(
        "mma.sync.aligned.m16n8k16.row.col.f32.f16.f16.f32 "
        "{%0,%1,%2,%3}, {%4,%5,%6,%7}, {%8,%9}, {%0,%1,%2,%3};"
        : "+f"(c[0]), "+f"(c[1]), "+f"(c[2]), "+f"(c[3])
        : "r"(a[0]), "r"(a[1]), "r"(a[2]), "r"(a[3]), "r"(b[0]), "r"(b[1]));
}
__device__ __forceinline__ void cpa16(void* dst, const void* g) {
    unsigned s = (unsigned)__cvta_generic_to_shared(dst);
    asm volatile("cp.async.ca.shared.global [%0], [%1], 16;"
                 :: "r"(s), "l"(g) : "memory");
}
__device__ __forceinline__ void cpa16p(void* dst, const void* g, bool ok) {
    unsigned s = (unsigned)__cvta_generic_to_shared(dst);
    int sz = ok ? 16 : 0;
    asm volatile("cp.async.ca.shared.global [%0], [%1], 16, %2;"
                 :: "r"(s), "l"(g), "r"(sz) : "memory");
}

// ---------------------------------------------------------------------------
// Mask normalization + per-batch 1/len. Single block, deterministic.
// ---------------------------------------------------------------------------
__global__ void mask_prepare(const unsigned char* __restrict__ raw) {
    __shared__ int s_nz1, s_f3;
    if (threadIdx.x == 0) { s_nz1 = 0; s_f3 = 0; }
    __syncthreads();
    int lnz = 0, lf = 0;
    for (int i = threadIdx.x; i < Mn; i += blockDim.x) {
        unsigned char v = raw[i];
        if ((i & 3) != 0 && v != 0) lnz++;
        if ((i & 3) == 3 && v == 0x3F) lf++;
    }
    atomicAdd(&s_nz1, lnz);
    atomicAdd(&s_f3, lf);
    __syncthreads();
    int mode = (s_f3 > 0) ? 2 : ((s_nz1 > 0) ? 0 : 1);  // 0=u8 1=i32 2=f32
    for (int i = threadIdx.x; i < Mn; i += blockDim.x) {
        unsigned char m;
        if (mode == 0)      m = (raw[i] != 0);
        else if (mode == 1) m = (((const int*)raw)[i] != 0);
        else                m = (((const float*)raw)[i] != 0.f);
        g_mask[i] = m;
    }
    __syncthreads();
    int w = threadIdx.x >> 5, l = threadIdx.x & 31;
    if (w < Bn) {
        int cnt = 0;
        for (int t = l; t < Tn; t += 32) cnt += (g_mask[w * Tn + t] == 0);
        for (int off = 16; off; off >>= 1)
            cnt += __shfl_down_sync(0xffffffffu, cnt, off);
        if (l == 0) g_cinv[w] = 1.f / (float)cnt;
    }
}

__global__ void tohalf(const float* __restrict__ in, __half* __restrict__ out,
                       int n) {
    int i = blockIdx.x * blockDim.x + threadIdx.x;
    if (i < n) out[i] = __float2half_rn(in[i]);
}

// Pack Wq/Wk -> fp16 [512,256]; biases (fp32) -> [512]
__global__ void wpack_qk(const float* __restrict__ Wq,
                         const float* __restrict__ Wk,
                         const float* __restrict__ bq,
                         const float* __restrict__ bk,
                         __half* __restrict__ W, float* __restrict__ b) {
    int idx = blockIdx.x * blockDim.x + threadIdx.x;
    if (idx < 2 * Dn * Dn) {
        const float* src = (idx < Dn * Dn) ? Wq : Wk;
        W[idx] = __float2half_rn(src[idx & (Dn * Dn - 1)]);
    }
    if (idx < 2 * Dn) b[idx] = (idx < Dn) ? bq[idx] : bk[idx - Dn];
}

// Conv weight re-layout + interleave: GEMM col j: even j -> a oc=j/2,
// odd j -> gate oc=256+j/2.   Wt[j][kk*256+ic] = cW[oc][ic][kk]
__global__ void wtrans(const float* __restrict__ cW, __half* __restrict__ Wt) {
    int idx = blockIdx.x * blockDim.x + threadIdx.x;
    if (idx >= 2 * Dn * Kc * Dn) return;
    int j = idx / (Kc * Dn);
    int k = idx - j * (Kc * Dn);
    int kk = k >> 8;
    int ic = k & 255;
    int oc = (j & 1) ? (256 + (j >> 1)) : (j >> 1);
    Wt[idx] = __float2half_rn(cW[((size_t)oc * Dn + ic) * Kc + kk]);
}

// ---------------------------------------------------------------------------
// FP16 tensor-core TN GEMM: C = epi( A[M,K](lda) @ B[N,K](ldb)^T )
// 128x128 tile, BK=32, 256 threads (8 warps of 64x32), cp.async double buffer.
// EPI: 0=+bias (half out), 1=mish(+bias) (half), 2=+bias+res (FLOAT out),
//      3=*scale (half), 4=conv GLU (half), 5=V transpose write (half)
// CONV: A rows gathered with time shift (implicit conv GEMM)
// ---------------------------------------------------------------------------
template <int EPI, bool CONV, bool MASKED>
__global__ void __launch_bounds__(256)
mma_gemm(const __half* __restrict__ A, const __half* __restrict__ Bm,
         const float* __restrict__ bias, const __half* __restrict__ res,
         void* __restrict__ Cv, int K, int lda, int ldb, int ldc,
         int Hdec, long sAb, long sAh, long sBb, long sBh, long sCb, long sCh,
         float scale) {
    int z = blockIdx.z;
    int zb = z / Hdec, zh = z - zb * Hdec;
    A  += zb * sAb + zh * sAh;
    Bm += zb * sBb + zh * sBh;

    __shared__ char sm[4 * TILE_B];          // A[2] then B[2]
    char* smB = sm + 2 * TILE_B;

    const int m0 = blockIdx.y * 128;
    const int n0 = blockIdx.x * 128;
    const int tid  = threadIdx.x;
    const int warp = tid >> 5, lane = tid & 31;
    const int wr = warp >> 2, wc = warp & 3;     // 2 x 4 warp grid
    const int gid = lane >> 2, tig = lane & 3;   // fragment coords

    auto load_tiles = [&](int buf, int kt) {
#pragma unroll
        for (int p = 0; p < 2; p++) {
            int idx = tid + p * 256;
            int row = idx >> 2, ch = idx & 3;    // ch: 16B chunk (8 halves)
            char* dA = sm + buf * TILE_B + row * ROW_B + ch * 16;
            if (CONV) {
                int dt = (kt >> 8) - 2;
                int m = m0 + row;
                int t = m & (Tn - 1);
                bool ok = (unsigned)(t + dt) < (unsigned)Tn;
                const __half* g = A + (size_t)(m + (ok ? dt : 0)) * lda +
                                  (kt & 255) + ch * 8;
                cpa16p(dA, g, ok);
            } else {
                cpa16(dA, A + (size_t)(m0 + row) * lda + kt + ch * 8);
            }
            char* dB = smB + buf * TILE_B + row * ROW_B + ch * 16;
            cpa16(dB, Bm + (size_t)(n0 + row) * ldb + kt + ch * 8);
        }
    };

    float acc[4][4][4];
#pragma unroll
    for (int i = 0; i < 4; i++)
#pragma unroll
        for (int j = 0; j < 4; j++)
#pragma unroll
            for (int q = 0; q < 4; q++) acc[i][j][q] = 0.f;

    load_tiles(0, 0);
    asm volatile("cp.async.commit_group;" ::: "memory");

    const int nIter = K >> 5;                    // BK = 32 halves
    for (int it = 0; it < nIter; it++) {
        int buf = it & 1;
        if (it + 1 < nIter) {
            load_tiles(buf ^ 1, (it + 1) << 5);
            asm volatile("cp.async.commit_group;" ::: "memory");
            asm volatile("cp.async.wait_group 1;" ::: "memory");
        } else {
            asm volatile("cp.async.wait_group 0;" ::: "memory");
        }
        __syncthreads();

        const unsigned* As = (const unsigned*)(sm + buf * TILE_B);
        const unsigned* Bs = (const unsigned*)(smB + buf * TILE_B);
#pragma unroll
        for (int ks = 0; ks < 2; ks++) {         // two k16 steps
            int kw = ks * 8;                     // word offset in row
            unsigned af[4][4];
#pragma unroll
            for (int mt = 0; mt < 4; mt++) {
                int mr = wr * 64 + mt * 16 + gid;
                af[mt][0] = As[mr * ROW_W + kw + tig];
                af[mt][1] = As[(mr + 8) * ROW_W + kw + tig];
                af[mt][2] = As[mr * ROW_W + kw + tig + 4];
                af[mt][3] = As[(mr + 8) * ROW_W + kw + tig + 4];
            }
            unsigned bfr[4][2];
#pragma unroll
            for (int nt = 0; nt < 4; nt++) {
                int nc = wc * 32 + nt * 8 + gid;
                bfr[nt][0] = Bs[nc * ROW_W + kw + tig];
                bfr[nt][1] = Bs[nc * ROW_W + kw + tig + 4];
            }
#pragma unroll
            for (int mt = 0; mt < 4; mt++)
#pragma unroll
                for (int nt = 0; nt < 4; nt++)
                    mma_f16(acc[mt][nt], af[mt], bfr[nt]);
        }
        __syncthreads();
    }

    // ---- epilogue ----
#pragma unroll
    for (int mt = 0; mt < 4; mt++) {
#pragma unroll
        for (int nt = 0; nt < 4; nt++) {
            int mbase = m0 + wr * 64 + mt * 16 + gid;
            int n = n0 + wc * 32 + nt * 8 + 2 * tig;
#pragma unroll
            for (int half_ = 0; half_ < 2; half_++) {
                int m = mbase + half_ * 8;
                float v0 = acc[mt][nt][half_ * 2 + 0];
                float v1 = acc[mt][nt][half_ * 2 + 1];
                if (EPI == 2) {
                    float* C = (float*)Cv + zb * sCb + zh * sCh;
                    v0 += bias[n]     + __half2float(res[(size_t)m * ldc + n]);
                    v1 += bias[n + 1] + __half2float(res[(size_t)m * ldc + n + 1]);
                    *(float2*)(C + (size_t)m * ldc + n) = make_float2(v0, v1);
                } else if (EPI == 4) {
                    __half* C = (__half*)Cv;
                    int i = n >> 1;              // even n = a, odd n = gate
                    float a = v0 + bias[i];
                    float g = v1 + bias[256 + i];
                    float v = __half2float(res[(size_t)m * 256 + i]) +
                              a * sigmoidf(g);
                    if (MASKED && g_mask[m]) v = 0.f;
                    C[(size_t)m * 256 + i] = __float2half_rn(v);
                } else if (EPI == 5) {
                    __half* C = (__half*)Cv;
                    int bb = m >> 10, t = m & (Tn - 1);
                    C[((size_t)((bb * 2 + (n >> 7)) * 128 + (n & 127))) * Tn + t] =
                        __float2half_rn(v0 + bias[n]);
                    C[((size_t)((bb * 2 + ((n + 1) >> 7)) * 128 + ((n + 1) & 127))) * Tn + t] =
                        __float2half_rn(v1 + bias[n + 1]);
                } else {
                    __half* C = (__half*)Cv + zb * sCb + zh * sCh;
                    if (EPI == 0)      { v0 += bias[n]; v1 += bias[n + 1]; }
                    else if (EPI == 1) { v0 = mishf(v0 + bias[n]);
                                         v1 = mishf(v1 + bias[n + 1]); }
                    else               { v0 *= scale; v1 *= scale; }
                    *(__half2*)(C + (size_t)m * ldc + n) =
                        __floats2half2_rn(v0, v1);
                }
            }
        }
    }
}

// ---------------------------------------------------------------------------
// Row softmax over 1024 fp16 keys with key-mask; in place, fp16 probs out.
// ---------------------------------------------------------------------------
__global__ void softmax_kernel(__half* __restrict__ Sc) {
    __shared__ float sred[8];
    int row = blockIdx.x;
    int b = row >> 11;
    __half2* s2 = (__half2*)(Sc + (size_t)row * Tn);
    const uchar4* mk4 = (const uchar4*)(g_mask + b * Tn);
    int tid = threadIdx.x, lane = tid & 31, wrp = tid >> 5;

    uchar4 m = mk4[tid];
    float2 va = __half22float2(s2[2 * tid]);
    float2 vb = __half22float2(s2[2 * tid + 1]);
    float f0 = m.x ? -1e30f : va.x;
    float f1 = m.y ? -1e30f : va.y;
    float f2 = m.z ? -1e30f : vb.x;
    float f3 = m.w ? -1e30f : vb.y;
    float mx = fmaxf(fmaxf(f0, f1), fmaxf(f2, f3));
#pragma unroll
    for (int o = 16; o; o >>= 1)
        mx = fmaxf(mx, __shfl_xor_sync(0xffffffffu, mx, o));
    if (lane == 0) sred[wrp] = mx;
    __syncthreads();
    if (wrp == 0) {
        float t = sred[lane & 7];
#pragma unroll
        for (int o = 4; o; o >>= 1)
            t = fmaxf(t, __shfl_xor_sync(0xffffffffu, t, o));
        if (lane == 0) sred[0] = t;
    }
    __syncthreads();
    mx = sred[0];

    float e0 = m.x ? 0.f : __expf(va.x - mx);
    float e1 = m.y ? 0.f : __expf(va.y - mx);
    float e2 = m.z ? 0.f : __expf(vb.x - mx);
    float e3 = m.w ? 0.f : __expf(vb.y - mx);
    float sum = (e0 + e1) + (e2 + e3);
#pragma unroll
    for (int o = 16; o; o >>= 1)
        sum += __shfl_xor_sync(0xffffffffu, sum, o);
    __syncthreads();
    if (lane == 0) sred[wrp] = sum;
    __syncthreads();
    if (wrp == 0) {
        float t = sred[lane & 7];
#pragma unroll
        for (int o = 4; o; o >>= 1)
            t += __shfl_xor_sync(0xffffffffu, t, o);
        if (lane == 0) sred[0] = t;
    }
    __syncthreads();
    float inv = 1.f / sred[0];
    s2[2 * tid]     = __floats2half2_rn(e0 * inv, e1 * inv);
    s2[2 * tid + 1] = __floats2half2_rn(e2 * inv, e3 * inv);
}

// Masked temporal partial sums: g_Sp[chunk][b,d] over 128 t's each.
__global__ void pool_kernel(const float* __restrict__ H5) {
    int b = blockIdx.x;
    int chunk = blockIdx.y;
    int d = threadIdx.x;
    float s = 0.f;
    int t0 = chunk * 128;
    for (int t = t0; t < t0 + 128; t++)
        if (!g_mask[b * Tn + t])
            s += H5[((size_t)b * Tn + t) * Dn + d];
    g_Sp[chunk][b * Dn + d] = s;
}

// out[b,n] = (S_b @ Wf^T)[n]/len_b + bf[n]
__global__ void final_kernel(const float* __restrict__ Wf,
                             const float* __restrict__ bf,
                             float* __restrict__ out) {
    int b = blockIdx.x;
    int n = threadIdx.x;
    __shared__ float sb[Dn];
    float s = 0.f;
#pragma unroll
    for (int c = 0; c < 8; c++) s += g_Sp[c][b * Dn + n];
    sb[n] = s;
    __syncthreads();
    float acc = 0.f;
    const float* w = Wf + (size_t)n * Dn;
#pragma unroll 8
    for (int k = 0; k < Dn; k++) acc = fmaf(sb[k], w[k], acc);
    out[b * Dn + n] = acc * g_cinv[b] + bf[n];
}

// ---------------------------------------------------------------------------
extern "C" void kernel_launch(void* const* d_in, const int* in_sizes, int n_in,
                              void* d_out, int out_size) {
    (void)in_sizes; (void)n_in; (void)out_size;
    const float* x   = (const float*)d_in[0];
    const unsigned char* mraw = (const unsigned char*)d_in[1];
    const float* W1  = (const float*)d_in[2];
    const float* b1  = (const float*)d_in[3];
    const float* W2  = (const float*)d_in[4];
    const float* b2  = (const float*)d_in[5];
    const float* cW1 = (const float*)d_in[6];
    const float* cb1 = (const float*)d_in[7];
    const float* cW2 = (const float*)d_in[8];
    const float* cb2 = (const float*)d_in[9];
    const float* Wq  = (const float*)d_in[10];
    const float* bq  = (const float*)d_in[11];
    const float* Wk  = (const float*)d_in[12];
    const float* bk  = (const float*)d_in[13];
    const float* Wv  = (const float*)d_in[14];
    const float* bv  = (const float*)d_in[15];
    const float* Wo  = (const float*)d_in[16];
    const float* bo  = (const float*)d_in[17];
    const float* Wf  = (const float*)d_in[18];
    const float* bf  = (const float*)d_in[19];
    float* out = (float*)d_out;

    __half *xh, *h1, *h2, *h3, *res, *qk, *vt, *attn, *scores;
    __half *wt1, *wt2, *w1h, *w2h, *woh, *wvh, *wqk;
    float *h5, *bqk;
    cudaGetSymbolAddress((void**)&xh, g_xh);
    cudaGetSymbolAddress((void**)&h1, g_h1);
    cudaGetSymbolAddress((void**)&h2, g_h2);
    cudaGetSymbolAddress((void**)&h3, g_h3);
    cudaGetSymbolAddress((void**)&res, g_res);
    cudaGetSymbolAddress((void**)&qk, g_qk);
    cudaGetSymbolAddress((void**)&vt, g_vt);
    cudaGetSymbolAddress((void**)&attn, g_attn);
    cudaGetSymbolAddress((void**)&h5, g_h5);
    cudaGetSymbolAddress((void**)&scores, g_scores);
    cudaGetSymbolAddress((void**)&wt1, g_wt1);
    cudaGetSymbolAddress((void**)&wt2, g_wt2);
    cudaGetSymbolAddress((void**)&w1h, g_w1h);
    cudaGetSymbolAddress((void**)&w2h, g_w2h);
    cudaGetSymbolAddress((void**)&woh, g_woh);
    cudaGetSymbolAddress((void**)&wvh, g_wvh);
    cudaGetSymbolAddress((void**)&wqk, g_wqk);
    cudaGetSymbolAddress((void**)&bqk, g_bqk);

    // 0) mask + fp16 conversions / packing
    mask_prepare<<<1, 1024>>>(mraw);
    tohalf<<<Mn * Dn / 256, 256>>>(x, xh, Mn * Dn);
    tohalf<<<Dn * Dn / 256, 256>>>(W1, w1h, Dn * Dn);
    tohalf<<<Dn * Dn / 256, 256>>>(W2, w2h, Dn * Dn);
    tohalf<<<Dn * Dn / 256, 256>>>(Wo, woh, Dn * Dn);
    tohalf<<<Dn * Dn / 256, 256>>>(Wv, wvh, Dn * Dn);
    wpack_qk<<<2 * Dn * Dn / 256, 256>>>(Wq, Wk, bq, bk, wqk, bqk);
    wtrans<<<(2 * Dn * Kc * Dn + 255) / 256, 256>>>(cW1, wt1);
    wtrans<<<(2 * Dn * Kc * Dn + 255) / 256, 256>>>(cW2, wt2);

    dim3 gDense(2, 128, 1);
    dim3 gConv(4, 128, 1);
    dim3 gQK(4, 128, 1);
    dim3 gVT(2, 128, 1);
    dim3 gScore(8, 8, 32);
    dim3 gPV(1, 8, 32);

    // 1) spectral MLP (Linear + Mish) x2
    mma_gemm<1, false, false><<<gDense, 256>>>(xh, w1h, b1, nullptr, h1,
        Dn, Dn, Dn, Dn, 1, 0, 0, 0, 0, 0, 0, 1.f);
    mma_gemm<1, false, false><<<gDense, 256>>>(h1, w2h, b2, nullptr, h2,
        Dn, Dn, Dn, Dn, 1, 0, 0, 0, 0, 0, 0, 1.f);

    // 2) Conv1dGLU x2 (implicit TN GEMM K=1280, GLU fused in epilogue)
    mma_gemm<4, true, false><<<gConv, 256>>>(h2, wt1, cb1, h2, h3,
        Kc * Dn, Dn, Kc * Dn, Dn, 1, 0, 0, 0, 0, 0, 0, 1.f);
    mma_gemm<4, true, true><<<gConv, 256>>>(h3, wt2, cb2, h3, res,
        Kc * Dn, Dn, Kc * Dn, Dn, 1, 0, 0, 0, 0, 0, 0, 1.f);

    // 3) q,k projection (N=512) + v projection written transposed
    mma_gemm<0, false, false><<<gQK, 256>>>(res, wqk, bqk, nullptr, qk,
        Dn, Dn, Dn, 2 * Dn, 1, 0, 0, 0, 0, 0, 0, 1.f);
    mma_gemm<5, false, false><<<gVT, 256>>>(res, wvh, bv, nullptr, vt,
        Dn, Dn, Dn, Tn, 1, 0, 0, 0, 0, 0, 0, 1.f);

    // 4) attention: scores = Q@K^T/temp, softmax, P@V^T (TN)
    const long sQb = (long)Tn * 2 * Dn, sQh = 128;
    const long sSb = 2L * Tn * Tn, sSh = (long)Tn * Tn;
    const long sVb = 2L * 128 * Tn, sVh = 128L * Tn;
    const long sCb = (long)Tn * Dn, sCh = 128;
    mma_gemm<3, false, false><<<gScore, 256>>>(qk, qk + Dn, nullptr, nullptr,
        scores, 128, 2 * Dn, 2 * Dn, Tn,
        Hn, sQb, sQh, sQb, sQh, sSb, sSh, SCALE_ATTN);
    softmax_kernel<<<Bn * Hn * Tn, 256>>>(scores);
    mma_gemm<3, false, false><<<gPV, 256>>>(scores, vt, nullptr, nullptr,
        attn, Tn, Tn, Tn, Dn,
        Hn, sSb, sSh, sVb, sVh, sCb, sCh, 1.f);

    // 5) output projection + residual (float out)
    mma_gemm<2, false, false><<<gDense, 256>>>(attn, woh, bo, res, h5,
        Dn, Dn, Dn, Dn, 1, 0, 0, 0, 0, 0, 0, 1.f);

    // 6) masked pool (partials) + tiny final GEMM (Wf folded after pooling)
    pool_kernel<<<dim3(Bn, 8), Dn>>>(h5);
    final_kernel<<<Bn, Dn>>>(Wf, bf, out);
}